// round 13
// baseline (speedup 1.0000x reference)
#include <cuda_runtime.h>
#include <cuda_bf16.h>

#define EMBED 32
#define NPW 8                 // nodes per warp
#define WARPS_PER_BLOCK 8
#define THREADS 256
#define NODES_PER_BLOCK (WARPS_PER_BLOCK * NPW)   // 64

__global__ __launch_bounds__(THREADS, 5)   // cap regs ~51: R10 showed 115 regs -> 22% occ disaster
void agg_kernel(const int* __restrict__ nodes,
                const int* __restrict__ glist,
                const int* __restrict__ alist,
                const float* __restrict__ u_emb,
                const float* __restrict__ g_emb,
                const float* __restrict__ a_emb,
                const float* __restrict__ W,
                const float* __restrict__ b,
                float* __restrict__ out,
                int n) {
    // Persistent shared:
    __shared__ float wt[32 * 33];        // wt[k*33+j] = W[j][64+k]  (Wu transposed, padded)
    __shared__ float gam[16 * EMBED];    // combined gender/age table (incl. bias)
    __shared__ int   ids[NODES_PER_BLOCK];
    // Union: table staging (2464 floats) first, then reused as xs (2048 floats).
    __shared__ __align__(16) float un[2464];
    // staging: Wt64 = un[0..2112)  (Wt64[k*33+j] = W[j*96+k], k<64)
    //          ges  = un[2112..2176), aes = un[2176..2432), bs = un[2432..2464)

    const int t    = threadIdx.x;
    const int lane = t & 31;
    const int wib  = t >> 5;
    const long gbase = (long)blockIdx.x * NODES_PER_BLOCK;

    // ---- stage: W cols 0..63 (for table), Wu cols 64..95 (for matvec), tables, ids ----
    for (int e = t; e < 32 * 64; e += THREADS) {
        int j = e >> 6, k = e & 63;                 // k fastest -> coalesced
        un[k * 33 + j] = W[j * 96 + k];
    }
    #pragma unroll
    for (int r = 0; r < 4; r++) {
        int e = t + r * THREADS;                    // 0..1023 = j*32+k
        int j = e >> 5, k = e & 31;
        wt[k * 33 + j] = W[j * 96 + 64 + k];
    }
    if (t < 64) un[2112 + t] = g_emb[t];
    un[2176 + t] = a_emb[t];                        // exactly 256 entries
    if (t < 32) un[2432 + t] = b[t];
    if (t < NODES_PER_BLOCK) {
        long idx = gbase + t;
        ids[t] = (idx < n) ? nodes[idx] : 0;
    }
    __syncthreads();

    // ---- per-block gamat table: 512 entries, 2 per thread, 64 FMA each ----
    #pragma unroll
    for (int r = 0; r < 2; r++) {
        int e  = t + r * THREADS;                   // 0..511
        int j  = e & 31;
        int ga = e >> 5;
        int g  = ga >> 3, a = ga & 7;
        float acc = un[2432 + j];
        #pragma unroll
        for (int k = 0; k < 32; k++) acc += un[2112 + g * 32 + k] * un[k * 33 + j];
        #pragma unroll
        for (int k = 0; k < 32; k++) acc += un[2176 + a * 32 + k] * un[(32 + k) * 33 + j];
        gam[ga * EMBED + j] = acc;
    }
    __syncthreads();        // gam/wt ready; staging region now dead -> reuse as xs

    float* xs = un;         // xs[(wib*NPW + i)*EMBED + lane]

    const long base = gbase + (long)wib * NPW;
    if (base < n) {
        // Node ids (broadcast LDS).
        int node[NPW];
        #pragma unroll
        for (int i = 0; i < NPW; i++) node[i] = ids[wib * NPW + i];

        // Batched random 4B gathers: 16 independent loads in flight.
        int g[NPW], a[NPW];
        #pragma unroll
        for (int i = 0; i < NPW; i++) {
            g[i] = __ldg(&glist[node[i]]);
            a[i] = __ldg(&alist[node[i]]);
        }

        // Coalesced row gather: one warp loads one full 128B u_emb row per i.
        #pragma unroll
        for (int i = 0; i < NPW; i++)
            xs[(wib * NPW + i) * EMBED + lane] = __ldg(&u_emb[(long)node[i] * EMBED + lane]);

        // Init from the block-local table (broadcast LDS).
        float acc[NPW];
        #pragma unroll
        for (int i = 0; i < NPW; i++)
            acc[i] = gam[((g[i] << 3) + a[i]) * EMBED + lane];

        __syncwarp();

        // Matvec: lane j computes out[node][j]. Weights from padded shared
        // (bank (k+lane)%32, conflict-free), x via broadcast LDS.128.
        #pragma unroll
        for (int c = 0; c < 4; c++) {
            float wc[8];
            #pragma unroll
            for (int q = 0; q < 8; q++) wc[q] = wt[(c * 8 + q) * 33 + lane];
            #pragma unroll
            for (int i = 0; i < NPW; i++) {
                const float* xrow = &xs[(wib * NPW + i) * EMBED + c * 8];
                float4 v0 = *(const float4*)(xrow);
                float4 v1 = *(const float4*)(xrow + 4);
                acc[i] += wc[0] * v0.x + wc[1] * v0.y + wc[2] * v0.z + wc[3] * v0.w
                        + wc[4] * v1.x + wc[5] * v1.y + wc[6] * v1.z + wc[7] * v1.w;
            }
        }

        #pragma unroll
        for (int i = 0; i < NPW; i++) {
            long idx = base + i;
            if (idx < n) out[idx * EMBED + lane] = fmaxf(acc[i], 0.f);
        }
    }
}

extern "C" void kernel_launch(void* const* d_in, const int* in_sizes, int n_in,
                              void* d_out, int out_size) {
    const int*   nodes = (const int*)d_in[0];
    const int*   glist = (const int*)d_in[1];
    const int*   alist = (const int*)d_in[2];
    const float* u_emb = (const float*)d_in[3];
    const float* g_emb = (const float*)d_in[4];
    const float* a_emb = (const float*)d_in[5];
    const float* W     = (const float*)d_in[6];
    const float* b     = (const float*)d_in[7];
    float* out = (float*)d_out;
    int n = in_sizes[0];

    int blocks = (n + NODES_PER_BLOCK - 1) / NODES_PER_BLOCK;
    agg_kernel<<<blocks, THREADS>>>(nodes, glist, alist, u_emb, g_emb, a_emb, W, b, out, n);
}

// round 14
// speedup vs baseline: 3.2958x; 3.2958x over previous
#include <cuda_runtime.h>
#include <cuda_bf16.h>

#define EMBED 32
#define NPW 8                 // nodes per warp
#define WARPS_PER_BLOCK 8
#define THREADS (WARPS_PER_BLOCK * 32)
#define NODES_PER_BLOCK (WARPS_PER_BLOCK * NPW)   // 64

// Combined precomputed table (global, filled by pre_kernel):
//   d_gamat[(g*8+a)*32 + j] = b[j] + sum_k g_emb[g][k]*W[j][k] + sum_k a_emb[a][k]*W[j][32+k]
__device__ float d_gamat[16 * EMBED];

// ---------------------------------------------------------------------------
// pre_kernel: 1 block, 512 threads. Stage everything in shared coalescedly,
// then each thread computes one (g,a,j) entry conflict-free.
// ---------------------------------------------------------------------------
__global__ __launch_bounds__(512)
void pre_kernel(const float* __restrict__ g_emb,
                const float* __restrict__ a_emb,
                const float* __restrict__ W,
                const float* __restrict__ b) {
    __shared__ float Wt[96 * 33];   // Wt[k*33+j] = W[j*96+k]; pad 33 -> bank (k+j)%32
    __shared__ float ges[64];       // g_emb 2x32
    __shared__ float aes[256];      // a_emb 8x32
    __shared__ float bs[32];

    const int t = threadIdx.x;

    for (int e = t; e < 32 * 96; e += 512) {
        int j = e / 96, k = e % 96;            // coalesced gmem read (k fastest)
        Wt[k * 33 + j] = W[e];
    }
    if (t < 64)  ges[t] = g_emb[t];
    for (int e = t; e < 256; e += 512) aes[e] = a_emb[e];
    if (t < 32)  bs[t] = b[t];
    __syncthreads();

    // t -> (ga, j): 16*32 = 512 entries. ga = t>>5, j = t&31
    const int j  = t & 31;
    const int ga = t >> 5;           // 0..15
    const int g  = ga >> 3;
    const int a  = ga & 7;

    float acc = bs[j];
    #pragma unroll
    for (int k = 0; k < 32; k++) acc += ges[g * 32 + k] * Wt[k * 33 + j];
    #pragma unroll
    for (int k = 0; k < 32; k++) acc += aes[a * 32 + k] * Wt[(32 + k) * 33 + j];
    d_gamat[ga * 32 + j] = acc;
}

// ---------------------------------------------------------------------------
// agg_kernel: block prologue loads Wu (W columns 64..95) transposed into
// shared; main loop does the gathers + matvec with shared-resident weights.
// __launch_bounds__(256, 6): force regs <= ~42 for 6 blocks/SM (R9 measured
// 48 regs -> 5 blocks -> occ 54%; this is the single knob changed vs R9).
// ---------------------------------------------------------------------------
__global__ __launch_bounds__(THREADS, 6)
void agg_kernel(const int* __restrict__ nodes,
                const int* __restrict__ glist,
                const int* __restrict__ alist,
                const float* __restrict__ u_emb,
                const float* __restrict__ W,
                float* __restrict__ out,
                int n) {
    __shared__ float wt[32 * 33];                  // wt[k*33+j] = Wu[j][k] = W[j*96+64+k]
    __shared__ int   ids[NODES_PER_BLOCK];
    __shared__ float xs[WARPS_PER_BLOCK][NPW][EMBED];

    const int t    = threadIdx.x;
    const int lane = t & 31;
    const int wib  = t >> 5;

    // --- block prologue (everyone participates; no early return before sync) ---
    // Wu load: 1024 floats, 4 per thread, coalesced within each W row segment.
    #pragma unroll
    for (int r = 0; r < 4; r++) {
        int e = t + r * THREADS;                   // 0..1023
        int j = e >> 5, k = e & 31;                // e = j*32+k, k fastest -> coalesced
        wt[k * 33 + j] = W[j * 96 + 64 + k];
    }
    {
        long idx = (long)blockIdx.x * NODES_PER_BLOCK + t;
        if (t < NODES_PER_BLOCK) ids[t] = (idx < n) ? nodes[idx] : 0;
    }
    __syncthreads();

    const long base = (long)blockIdx.x * NODES_PER_BLOCK + (long)wib * NPW;
    if (base < n) {
        // Node ids from shared (broadcast LDS, 1 wf each).
        int node[NPW];
        #pragma unroll
        for (int i = 0; i < NPW; i++) node[i] = ids[wib * NPW + i];

        // Batched second-level gathers: 16 independent uniform LDGs in flight.
        int g[NPW], a[NPW];
        #pragma unroll
        for (int i = 0; i < NPW; i++) {
            g[i] = __ldg(&glist[node[i]]);
            a[i] = __ldg(&alist[node[i]]);
        }

        // Coalesced row gather: one warp loads one full 128B u_emb row per i.
        #pragma unroll
        for (int i = 0; i < NPW; i++)
            xs[wib][i][lane] = __ldg(&u_emb[(long)node[i] * EMBED + lane]);

        // Init from the tiny global table (broadcast LDG, L1-resident 2KB).
        float acc[NPW];
        #pragma unroll
        for (int i = 0; i < NPW; i++)
            acc[i] = __ldg(&d_gamat[((g[i] << 3) + a[i]) * EMBED + lane]);

        __syncwarp();

        // Matvec: lane j computes out[node][j]. Weights streamed from shared in
        // k-chunks of 8 (conflict-free: bank = (k+lane)%32), x via broadcast
        // LDS.128. Low register pressure keeps occupancy up.
        #pragma unroll
        for (int c = 0; c < 4; c++) {
            float wc[8];
            #pragma unroll
            for (int q = 0; q < 8; q++) wc[q] = wt[(c * 8 + q) * 33 + lane];
            #pragma unroll
            for (int i = 0; i < NPW; i++) {
                float4 v0 = *(const float4*)&xs[wib][i][c * 8];
                float4 v1 = *(const float4*)&xs[wib][i][c * 8 + 4];
                acc[i] += wc[0] * v0.x + wc[1] * v0.y + wc[2] * v0.z + wc[3] * v0.w
                        + wc[4] * v1.x + wc[5] * v1.y + wc[6] * v1.z + wc[7] * v1.w;
            }
        }

        #pragma unroll
        for (int i = 0; i < NPW; i++) {
            long idx = base + i;
            if (idx < n) out[idx * EMBED + lane] = fmaxf(acc[i], 0.f);
        }
    }
}

extern "C" void kernel_launch(void* const* d_in, const int* in_sizes, int n_in,
                              void* d_out, int out_size) {
    const int*   nodes = (const int*)d_in[0];
    const int*   glist = (const int*)d_in[1];
    const int*   alist = (const int*)d_in[2];
    const float* u_emb = (const float*)d_in[3];
    const float* g_emb = (const float*)d_in[4];
    const float* a_emb = (const float*)d_in[5];
    const float* W     = (const float*)d_in[6];
    const float* b     = (const float*)d_in[7];
    float* out = (float*)d_out;
    int n = in_sizes[0];

    pre_kernel<<<1, 512>>>(g_emb, a_emb, W, b);

    int blocks = (n + NODES_PER_BLOCK - 1) / NODES_PER_BLOCK;
    agg_kernel<<<blocks, THREADS>>>(nodes, glist, alist, u_emb, W, out, n);
}